// round 15
// baseline (speedup 1.0000x reference)
#include <cuda_runtime.h>
#include <cuda_bf16.h>
#include <cstdint>

// Fixed problem constants
#define PH 7
#define PW 7
#define C_CH 256
#define H_FEAT 200
#define W_FEAT 272
#define HW (H_FEAT*W_FEAT)
#define SCALE 0.25f

#define CH_PER_BLOCK 64
#define CHUNKS (C_CH / CH_PER_BLOCK)   // 4
#define NTHREADS 224                   // 7 warps = 7 bin rows
#define DEPTH 8                        // cp.async pipeline stages (channels)

__device__ __forceinline__ void cp_async4(unsigned int saddr, const float* gaddr) {
    asm volatile("cp.async.ca.shared.global [%0], [%1], 4;\n"
                 :: "r"(saddr), "l"(gaddr));
}
__device__ __forceinline__ void cp_commit() {
    asm volatile("cp.async.commit_group;\n" ::: "memory");
}
__device__ __forceinline__ void cp_wait6() {
    asm volatile("cp.async.wait_group 6;\n" ::: "memory");
}

__global__ __launch_bounds__(NTHREADS) void roi_align_async(
    const float* __restrict__ feat,
    const float* __restrict__ rois,
    float* __restrict__ out,
    int n_rois)
{
    // Per-warp staging ring: [wid][slot][row][lane] floats, row-major so both
    // the async STS and the LDS reads are conflict-free.
    __shared__ float sbuf[7 * DEPTH * 4 * 32];   // 28 KB

    const int roi   = blockIdx.x % n_rois;
    const int chunk = blockIdx.x / n_rois;
    const int c0    = chunk * CH_PER_BLOCK;

    const int t    = threadIdx.x;
    const int wid  = t >> 5;            // bin row 0..6
    const int lane = t & 31;
    const int sx   = lane & 15;         // sample col (14,15 idle -> clamped)
    const int sxe  = min(sx, 13);
    const bool hi16 = (lane & 16) != 0; // x-high corner half

    // ---- per-ROI setup ----
    const float* r = rois + roi * 5;
    const int   b   = (int)r[0];
    const float swc = r[1] * SCALE;
    const float shc = r[2] * SCALE;
    const float ewc = r[3] * SCALE;
    const float ehc = r[4] * SCALE;
    const float bin_w = fmaxf(ewc - swc, 1.0f) / PW;
    const float bin_h = fmaxf(ehc - shc, 1.0f) / PH;

    float x  = swc + ((float)sxe + 0.5f) * 0.5f * bin_w;
    float vx = (x > -1.0f && x < (float)W_FEAT) ? 1.0f : 0.0f;
    float xc = fminf(fmaxf(x, 0.0f), (float)(W_FEAT - 1));
    int   xl = (int)floorf(xc);
    int   xh = min(xl + 1, W_FEAT - 1);
    float lx = xc - (float)xl;
    const int   xcol = hi16 ? xh : xl;
    float wx = (hi16 ? lx : (1.0f - lx)) * vx * 0.25f;  // 0.25 prefolded
    if (sx >= 14) wx = 0.0f;

    const int sy0 = wid * 2;
    float y0  = shc + ((float)sy0 + 0.5f) * 0.5f * bin_h;
    float vy0 = (y0 > -1.0f && y0 < (float)H_FEAT) ? 1.0f : 0.0f;
    float yc0 = fminf(fmaxf(y0, 0.0f), (float)(H_FEAT - 1));
    int   yl0 = (int)floorf(yc0);
    float ly0 = yc0 - (float)yl0;
    const int ol0 = yl0 * W_FEAT;
    const int oh0 = min(yl0 + 1, H_FEAT - 1) * W_FEAT;
    const float wly0 = ly0 * vy0;
    const float why0 = (1.0f - ly0) * vy0;

    float y1  = shc + ((float)(sy0 + 1) + 0.5f) * 0.5f * bin_h;
    float vy1 = (y1 > -1.0f && y1 < (float)H_FEAT) ? 1.0f : 0.0f;
    float yc1 = fminf(fmaxf(y1, 0.0f), (float)(H_FEAT - 1));
    int   yl1 = (int)floorf(yc1);
    float ly1 = yc1 - (float)yl1;
    const int ol1 = yl1 * W_FEAT;
    const int oh1 = min(yl1 + 1, H_FEAT - 1) * W_FEAT;
    const float wly1 = ly1 * vy1;
    const float why1 = (1.0f - ly1) * vy1;

    // Four row-base pointers (this lane's x column folded in).
    const float* fbase = feat + (b * C_CH + c0) * HW + xcol;
    const float* p00 = fbase + ol0;
    const float* p01 = fbase + oh0;
    const float* p10 = fbase + ol1;
    const float* p11 = fbase + oh1;

    // smem addresses for this warp/lane
    float* wbuf = sbuf + wid * (DEPTH * 4 * 32) + lane;      // + slot*128 + row*32
    const unsigned int sb = (unsigned int)__cvta_generic_to_shared(wbuf);

    const bool writer = ((lane & 1) == 0) && ((lane & 15) < 14);
    const int obase = (roi * C_CH + c0 + (lane >> 4)) * (PH * PW)
                    + wid * PW + ((lane & 15) >> 1);

    // ---- prologue: fill DEPTH stages ----
    #pragma unroll
    for (int ch = 0; ch < DEPTH; ch++) {
        const unsigned int sa = sb + (ch & (DEPTH - 1)) * 512;
        cp_async4(sa,        p00 + ch * HW);
        cp_async4(sa + 128,  p01 + ch * HW);
        cp_async4(sa + 256,  p10 + ch * HW);
        cp_async4(sa + 384,  p11 + ch * HW);
        cp_commit();
    }

    // ---- pipelined main loop: consume 2 channels, refill 2 stages ----
    #pragma unroll 4
    for (int c = 0; c < CH_PER_BLOCK; c += 2) {
        cp_wait6();   // stages c and c+1 complete (8 + c committed, pending<=6)

        float* pA = wbuf + (c & (DEPTH - 1)) * 128;
        float* pB = wbuf + ((c + 1) & (DEPTH - 1)) * 128;
        float a0A = pA[0], b0A = pA[32], a1A = pA[64], b1A = pA[96];
        float a0B = pB[0], b0B = pB[32], a1B = pB[64], b1B = pB[96];

        // refill (empty commits past the end keep group accounting constant)
        {
            int ch = c + DEPTH;
            const unsigned int sa = sb + (ch & (DEPTH - 1)) * 512;
            if (ch < CH_PER_BLOCK) {
                cp_async4(sa,        p00 + ch * HW);
                cp_async4(sa + 128,  p01 + ch * HW);
                cp_async4(sa + 256,  p10 + ch * HW);
                cp_async4(sa + 384,  p11 + ch * HW);
            }
            cp_commit();
            ch = c + DEPTH + 1;
            const unsigned int sa2 = sb + (ch & (DEPTH - 1)) * 512;
            if (ch < CH_PER_BLOCK) {
                cp_async4(sa2,       p00 + ch * HW);
                cp_async4(sa2 + 128, p01 + ch * HW);
                cp_async4(sa2 + 256, p10 + ch * HW);
                cp_async4(sa2 + 384, p11 + ch * HW);
            }
            cp_commit();
        }

        // compute + pair-fold (one shfl set serves both channels)
        float sA = why0 * a0A + wly0 * b0A + why1 * a1A + wly1 * b1A;
        float sB = why0 * a0B + wly0 * b0B + why1 * a1B + wly1 * b1B;
        float vA = wx * sA;
        float vB = wx * sB;
        float sel = hi16 ? vA : vB;
        float tt  = __shfl_xor_sync(0xffffffffu, sel, 16);
        float v2  = (hi16 ? vB : vA) + tt;
        float uu  = __shfl_xor_sync(0xffffffffu, v2, 1);
        float v3  = v2 + uu;
        if (writer) out[obase + c * (PH * PW)] = v3;
    }
}

extern "C" void kernel_launch(void* const* d_in, const int* in_sizes, int n_in,
                              void* d_out, int out_size) {
    const float* feat = (const float*)d_in[0];
    const float* rois = (const float*)d_in[1];
    float* out = (float*)d_out;

    int n_rois = in_sizes[1] / 5;
    int blocks = n_rois * CHUNKS;
    roi_align_async<<<blocks, NTHREADS>>>(feat, rois, out, n_rois);
}